// round 5
// baseline (speedup 1.0000x reference)
#include <cuda_runtime.h>

#define NN 100000
#define NE 1600000

// ---------------- scratch (static __device__ — allocation-free) ----------------
__device__ int    g_deg[NN];
__device__ int    g_cursor[NN];
__device__ int    g_rowptr[NN + 1];
__device__ int    g_bsum[256];
__device__ int    g_bsrc[NE];
__device__ float4 g_battr[NE];
__device__ float  g_xd[NN * 64];
__device__ float  g_xs[NN * 64];
__device__ float  g_h1[NN * 64];
__device__ float  g_h2[NN * 64];
__device__ float  g_hn[NN * 16];
__device__ float  g_gout[NN * 16];
// folded weights
__device__ float  g_Wc0[4 * 16],  g_xb0[16];
__device__ float  g_Wc1[4 * 64],  g_xb1[64];
__device__ float  g_Wcomb0[96 * 64],  g_bcomb0[64];
__device__ float  g_Wcomb1[384 * 64], g_bcomb1[64];

// ---------------- CSR build ----------------
__global__ void k_zero() {
    int i = blockIdx.x * blockDim.x + threadIdx.x;
    if (i < NN) { g_deg[i] = 0; g_cursor[i] = 0; }
}

__global__ void k_count(const int* __restrict__ dst) {
    int e = blockIdx.x * blockDim.x + threadIdx.x;
    if (e < NE) atomicAdd(&g_deg[dst[e]], 1);
}

__global__ void k_scan1() {
    __shared__ int s[1024];
    int i = blockIdx.x * 1024 + threadIdx.x;
    int v = (i < NN) ? g_deg[i] : 0;
    s[threadIdx.x] = v;
    __syncthreads();
    for (int off = 1; off < 1024; off <<= 1) {
        int t = (threadIdx.x >= off) ? s[threadIdx.x - off] : 0;
        __syncthreads();
        s[threadIdx.x] += t;
        __syncthreads();
    }
    if (i < NN) g_rowptr[i] = s[threadIdx.x] - v;   // exclusive within block
    if (threadIdx.x == 1023) g_bsum[blockIdx.x] = s[1023];
}

__global__ void k_scan2(int nb) {
    __shared__ int s[128];
    int t = threadIdx.x;
    int v = (t < nb) ? g_bsum[t] : 0;
    s[t] = v;
    __syncthreads();
    for (int off = 1; off < 128; off <<= 1) {
        int u = (t >= off) ? s[t - off] : 0;
        __syncthreads();
        s[t] += u;
        __syncthreads();
    }
    if (t < nb) g_bsum[t] = s[t] - v;   // exclusive block offsets
}

__global__ void k_scan3() {
    int i = blockIdx.x * 1024 + threadIdx.x;
    if (i < NN) g_rowptr[i] += g_bsum[blockIdx.x];
    if (i == 0) g_rowptr[NN] = NE;
}

__global__ void k_scatter(const int* __restrict__ src, const int* __restrict__ dst,
                          const float* __restrict__ ea) {
    int e = blockIdx.x * blockDim.x + threadIdx.x;
    if (e >= NE) return;
    int d = dst[e];
    int p = g_rowptr[d] + atomicAdd(&g_cursor[d], 1);
    g_bsrc[p]  = src[e];
    g_battr[p] = ((const float4*)ea)[e];
}

// ---------------- weight folding ----------------
__global__ void k_fold_edge(const float* __restrict__ We, const float* __restrict__ be,
                            const float* __restrict__ Wpre, const float* __restrict__ bpre,
                            int F, int layer) {
    int f = blockIdx.x * blockDim.x + threadIdx.x;
    if (f >= F) return;
    float a0 = 0, a1 = 0, a2 = 0, a3 = 0, b = bpre[f];
    for (int j = 0; j < F; j++) {
        float wv = Wpre[(2 * F + j) * F + f];
        a0 = fmaf(We[0 * F + j], wv, a0);
        a1 = fmaf(We[1 * F + j], wv, a1);
        a2 = fmaf(We[2 * F + j], wv, a2);
        a3 = fmaf(We[3 * F + j], wv, a3);
        b  = fmaf(be[j], wv, b);
    }
    float* Wc = layer ? g_Wc1 : g_Wc0;
    float* xb = layer ? g_xb1 : g_xb0;
    Wc[0 * F + f] = a0; Wc[1 * F + f] = a1; Wc[2 * F + f] = a2; Wc[3 * F + f] = a3;
    xb[f] = b;
}

__global__ void k_fold_post(const float* __restrict__ Wpost, const float* __restrict__ bpost,
                            const float* __restrict__ Wlin, const float* __restrict__ blin,
                            int Kc, int layer) {
    int idx = blockIdx.x * blockDim.x + threadIdx.x;
    int total = Kc * 64;
    float* Wcomb = layer ? g_Wcomb1 : g_Wcomb0;
    float* bcomb = layer ? g_bcomb1 : g_bcomb0;
    if (idx < total) {
        int k = idx >> 6, f = idx & 63;
        float a = 0;
        for (int j = 0; j < 64; j++) a = fmaf(Wpost[k * 64 + j], Wlin[j * 64 + f], a);
        Wcomb[idx] = a;
    } else if (idx < total + 64) {
        int f = idx - total;
        float a = blin[f];
        for (int j = 0; j < 64; j++) a = fmaf(bpost[j], Wlin[j * 64 + f], a);
        bcomb[f] = a;
    }
}

// ---------------- layer-0 precompute: xd0/xs0 ----------------
__global__ void k_xdxs0(const float* __restrict__ x, const float* __restrict__ Wpre0) {
    int t = blockIdx.x * blockDim.x + threadIdx.x;
    if (t >= NN * 32) return;
    int v = t >> 5, l = t & 31, f = l & 15;
    int rbase = (l < 16) ? 0 : 16;
    float acc = (l < 16) ? g_xb0[f] : 0.f;
    const float* xr = x + v * 16;
    #pragma unroll
    for (int j = 0; j < 16; j++)
        acc = fmaf(xr[j], Wpre0[(rbase + j) * 16 + f], acc);
    if (l < 16) g_xd[v * 16 + f] = acc;
    else        g_xs[v * 16 + f] = acc;
}

// ================ FUSED PNA layer 0: agg (F=16) + GEMM K=96 -> h1 ================
// 64 nodes/block, 256 threads. Dynamic SMEM: sA[64][100] + sB[96][68]
#define P0_SA_STRIDE 100
#define P0_SB_STRIDE 68
#define P0_SMEM ((64 * P0_SA_STRIDE + 96 * P0_SB_STRIDE) * 4)

__global__ __launch_bounds__(256) void k_pna0(const float* __restrict__ x) {
    extern __shared__ float sm0[];
    float* sA = sm0;                           // 64 x 100 (cols: x 0..15 | s 16 | mean 32 | mx 48 | mn 64 | sd 80)
    float* sB = sm0 + 64 * P0_SA_STRIDE;       // 96 x 68
    int tid = threadIdx.x;
    int nodeBase = blockIdx.x * 64;

    for (int i = tid; i < 96 * 64; i += 256)
        sB[(i >> 6) * P0_SB_STRIDE + (i & 63)] = g_Wcomb0[i];
    for (int i = tid; i < 64 * 16; i += 256) {
        int r = i >> 4, c = i & 15, v = nodeBase + r;
        sA[r * P0_SA_STRIDE + c] = (v < NN) ? x[v * 16 + c] : 0.f;
    }

    // ---- aggregation phase: 16 lanes/node, 16 nodes in parallel, 4 rounds ----
    int f = tid & 15, grp = tid >> 4;
    float w0 = g_Wc0[f], w1 = g_Wc0[16 + f], w2 = g_Wc0[32 + f], w3 = g_Wc0[48 + f];
    for (int rnd = 0; rnd < 4; rnd++) {
        int lr = rnd * 16 + grp;
        int v = nodeBase + lr;
        float s = 0, sq = 0, mx = -3.402823e38f, mn = 3.402823e38f;
        int cnt = 0;
        if (v < NN) {
            int rs = g_rowptr[v], re = g_rowptr[v + 1];
            cnt = re - rs;
            float xdv = g_xd[v * 16 + f];
            #pragma unroll 2
            for (int e = rs; e < re; e++) {
                int sid = g_bsrc[e];
                float4 a = g_battr[e];
                float m = xdv + g_xs[sid * 16 + f];
                m = fmaf(a.x, w0, fmaf(a.y, w1, fmaf(a.z, w2, fmaf(a.w, w3, m))));
                s += m; sq = fmaf(m, m, sq); mx = fmaxf(mx, m); mn = fminf(mn, m);
            }
        }
        float den = (float)(cnt > 0 ? cnt : 1);
        float mean = s / den;
        float sd = sqrtf(fmaxf(sq / den - mean * mean, 0.f) + 1e-5f);
        if (cnt == 0) { mx = 0.f; mn = 0.f; }
        float* o = sA + lr * P0_SA_STRIDE + 16 + f;
        o[0] = s; o[16] = mean; o[32] = mx; o[48] = mn; o[64] = sd;
    }
    __syncthreads();

    // ---- GEMM phase: C[64,64] = sA[64,96] @ sB[96,64]; microtile 2 rows x (4+4) cols ----
    int cg = tid & 7, rq = tid >> 3;           // rq 0..31, rows {rq, rq+32}; cols {cg*4.., 32+cg*4..}
    float acc[2][8];
    #pragma unroll
    for (int i = 0; i < 2; i++)
        #pragma unroll
        for (int j = 0; j < 8; j++) acc[i][j] = 0.f;

    #pragma unroll 4
    for (int k = 0; k < 96; k++) {
        float a0 = sA[rq * P0_SA_STRIDE + k];
        float a1 = sA[(rq + 32) * P0_SA_STRIDE + k];
        float4 b0 = *(const float4*)&sB[k * P0_SB_STRIDE + cg * 4];
        float4 b1 = *(const float4*)&sB[k * P0_SB_STRIDE + 32 + cg * 4];
        float bb[8] = {b0.x, b0.y, b0.z, b0.w, b1.x, b1.y, b1.z, b1.w};
        #pragma unroll
        for (int j = 0; j < 8; j++) {
            acc[0][j] = fmaf(a0, bb[j], acc[0][j]);
            acc[1][j] = fmaf(a1, bb[j], acc[1][j]);
        }
    }
    // epilogue: bias + relu -> g_h1
    float bias[8];
    #pragma unroll
    for (int j = 0; j < 4; j++) {
        bias[j]     = g_bcomb0[cg * 4 + j];
        bias[4 + j] = g_bcomb0[32 + cg * 4 + j];
    }
    #pragma unroll
    for (int i = 0; i < 2; i++) {
        int v = nodeBase + rq + i * 32;
        if (v < NN) {
            float4 o0, o1;
            float* p0 = (float*)&o0; float* p1 = (float*)&o1;
            #pragma unroll
            for (int j = 0; j < 4; j++) {
                p0[j] = fmaxf(acc[i][j]     + bias[j],     0.f);
                p1[j] = fmaxf(acc[i][4 + j] + bias[4 + j], 0.f);
            }
            *(float4*)&g_h1[v * 64 + cg * 4]      = o0;
            *(float4*)&g_h1[v * 64 + 32 + cg * 4] = o1;
        }
    }
}

// ================ FUSED PNA layer 1: agg (F=64) + GEMM K=384 -> h2 ================
// 32 nodes/block, 256 threads. Dynamic SMEM: sA[32][392] + sB[64][68]
#define P1_SA_STRIDE 392
#define P1_SB_STRIDE 68
#define P1_SMEM ((32 * P1_SA_STRIDE + 64 * P1_SB_STRIDE) * 4)

__global__ __launch_bounds__(256) void k_pna1() {
    extern __shared__ float sm1[];
    float* sA = sm1;                           // 32 x 392 (cols: h1 0..63 | s 64 | mean 128 | mx 192 | mn 256 | sd 320)
    float* sB = sm1 + 32 * P1_SA_STRIDE;       // 64 x 68 (one K-chunk of Wcomb1)
    int tid = threadIdx.x;
    int nodeBase = blockIdx.x * 32;

    for (int i = tid; i < 32 * 64; i += 256) {
        int r = i >> 6, c = i & 63, v = nodeBase + r;
        sA[r * P1_SA_STRIDE + c] = (v < NN) ? g_h1[v * 64 + c] : 0.f;
    }

    // ---- aggregation phase: 64 lanes/node, 4 nodes in parallel, 8 rounds ----
    int f = tid & 63, grp = tid >> 6;
    float w0 = g_Wc1[f], w1 = g_Wc1[64 + f], w2 = g_Wc1[128 + f], w3 = g_Wc1[192 + f];
    for (int rnd = 0; rnd < 8; rnd++) {
        int lr = rnd * 4 + grp;
        int v = nodeBase + lr;
        float s = 0, sq = 0, mx = -3.402823e38f, mn = 3.402823e38f;
        int cnt = 0;
        if (v < NN) {
            int rs = g_rowptr[v], re = g_rowptr[v + 1];
            cnt = re - rs;
            float xdv = g_xd[v * 64 + f];
            #pragma unroll 2
            for (int e = rs; e < re; e++) {
                int sid = g_bsrc[e];
                float4 a = g_battr[e];
                float m = xdv + g_xs[sid * 64 + f];
                m = fmaf(a.x, w0, fmaf(a.y, w1, fmaf(a.z, w2, fmaf(a.w, w3, m))));
                s += m; sq = fmaf(m, m, sq); mx = fmaxf(mx, m); mn = fminf(mn, m);
            }
        }
        float den = (float)(cnt > 0 ? cnt : 1);
        float mean = s / den;
        float sd = sqrtf(fmaxf(sq / den - mean * mean, 0.f) + 1e-5f);
        if (cnt == 0) { mx = 0.f; mn = 0.f; }
        float* o = sA + lr * P1_SA_STRIDE + 64 + f;
        o[0] = s; o[64] = mean; o[128] = mx; o[192] = mn; o[256] = sd;
    }

    // ---- GEMM phase: C[32,64] = sA[32,384] @ Wcomb1[384,64], K chunks of 64 ----
    int cg = tid & 7, rq = tid >> 3;           // rq 0..31 (1 row); cols {cg*4.., 32+cg*4..}
    float acc[8];
    #pragma unroll
    for (int j = 0; j < 8; j++) acc[j] = 0.f;

    for (int kc = 0; kc < 6; kc++) {
        __syncthreads();                       // agg done (kc=0) / prior sB reads done
        for (int i = tid; i < 64 * 64; i += 256) {
            int k = i >> 6, c = i & 63;
            sB[k * P1_SB_STRIDE + c] = g_Wcomb1[(kc * 64 + k) * 64 + c];
        }
        __syncthreads();
        const float* aRow = sA + rq * P1_SA_STRIDE + kc * 64;
        #pragma unroll 8
        for (int k = 0; k < 64; k++) {
            float a = aRow[k];
            float4 b0 = *(const float4*)&sB[k * P1_SB_STRIDE + cg * 4];
            float4 b1 = *(const float4*)&sB[k * P1_SB_STRIDE + 32 + cg * 4];
            acc[0] = fmaf(a, b0.x, acc[0]);
            acc[1] = fmaf(a, b0.y, acc[1]);
            acc[2] = fmaf(a, b0.z, acc[2]);
            acc[3] = fmaf(a, b0.w, acc[3]);
            acc[4] = fmaf(a, b1.x, acc[4]);
            acc[5] = fmaf(a, b1.y, acc[5]);
            acc[6] = fmaf(a, b1.z, acc[6]);
            acc[7] = fmaf(a, b1.w, acc[7]);
        }
    }
    // epilogue: bias + relu -> g_h2
    int v = nodeBase + rq;
    if (v < NN) {
        float4 o0, o1;
        float* p0 = (float*)&o0; float* p1 = (float*)&o1;
        #pragma unroll
        for (int j = 0; j < 4; j++) {
            p0[j] = fmaxf(acc[j]     + g_bcomb1[cg * 4 + j],      0.f);
            p1[j] = fmaxf(acc[4 + j] + g_bcomb1[32 + cg * 4 + j], 0.f);
        }
        *(float4*)&g_h2[v * 64 + cg * 4]      = o0;
        *(float4*)&g_h2[v * 64 + 32 + cg * 4] = o1;
    }
}

// ---------------- tiled fp32 GEMM (kept for xd1/xs1): C[M,64] = A[M,K] @ W[K,64] ----------------
template<int K, bool RELU>
__global__ __launch_bounds__(256) void k_gemm64(
    const float* __restrict__ A, int lda,
    const float* __restrict__ W,
    const float* __restrict__ bias,
    float* __restrict__ C, int ldc,
    int M)
{
    __shared__ float As[16][68];
    __shared__ float Bs[16][64];
    int tid = threadIdx.x;
    int tx = tid & 15, ty = tid >> 4;
    int rowBase = blockIdx.x * 64;
    float acc[4][4];
    #pragma unroll
    for (int i = 0; i < 4; i++)
        #pragma unroll
        for (int j = 0; j < 4; j++) acc[i][j] = 0.f;

    int ka = tid & 15, ra = tid >> 4;
    int cb = tid & 63, kb = tid >> 6;

    for (int kc = 0; kc < K; kc += 16) {
        #pragma unroll
        for (int i = 0; i < 4; i++) {
            int r = ra + i * 16;
            int gr = rowBase + r;
            As[ka][r] = (gr < M) ? A[gr * lda + kc + ka] : 0.f;
        }
        #pragma unroll
        for (int i = 0; i < 4; i++)
            Bs[kb + i * 4][cb] = W[(kc + kb + i * 4) * 64 + cb];
        __syncthreads();
        #pragma unroll
        for (int k = 0; k < 16; k++) {
            float4 b4 = *(const float4*)&Bs[k][tx * 4];
            float4 a4 = *(const float4*)&As[k][ty * 4];
            float av[4] = {a4.x, a4.y, a4.z, a4.w};
            float bv[4] = {b4.x, b4.y, b4.z, b4.w};
            #pragma unroll
            for (int i = 0; i < 4; i++)
                #pragma unroll
                for (int j = 0; j < 4; j++)
                    acc[i][j] = fmaf(av[i], bv[j], acc[i][j]);
        }
        __syncthreads();
    }

    int c0 = tx * 4;
    float bv[4];
    #pragma unroll
    for (int j = 0; j < 4; j++) bv[j] = bias ? bias[c0 + j] : 0.f;
    #pragma unroll
    for (int i = 0; i < 4; i++) {
        int gr = rowBase + ty * 4 + i;
        if (gr < M) {
            float4 o;
            float* po = (float*)&o;
            #pragma unroll
            for (int j = 0; j < 4; j++) {
                float v = acc[i][j] + bv[j];
                if (RELU) v = fmaxf(v, 0.f);
                po[j] = v;
            }
            *(float4*)&C[gr * ldc + c0] = o;
        }
    }
}

// ---------------- GCN ----------------
__global__ __launch_bounds__(256) void k_gcn_hn(const float* __restrict__ Wg) {
    __shared__ float w[64 * 16];
    int tid = threadIdx.x;
    for (int i = tid; i < 1024; i += 256) w[i] = Wg[i];
    __syncthreads();
    int v = blockIdx.x * 16 + (tid >> 4);
    int f = tid & 15;
    if (v >= NN) return;
    const float* h = g_h2 + v * 64;
    float acc = 0;
    #pragma unroll 8
    for (int j = 0; j < 64; j++) acc = fmaf(h[j], w[j * 16 + f], acc);
    float dinv = rsqrtf((float)(g_deg[v] + 1));
    g_hn[v * 16 + f] = acc * dinv;
}

__global__ __launch_bounds__(256) void k_gcn_agg(const float* __restrict__ bg) {
    int tid = threadIdx.x;
    int v = blockIdx.x * 16 + (tid >> 4);
    int f = tid & 15;
    if (v >= NN) return;
    int rs = g_rowptr[v], re = g_rowptr[v + 1];
    float s = g_hn[v * 16 + f];                 // self loop
    #pragma unroll 2
    for (int e = rs; e < re; e++)
        s += g_hn[g_bsrc[e] * 16 + f];
    float dinv = rsqrtf((float)(g_deg[v] + 1));
    g_gout[v * 16 + f] = s * dinv + bg[f];
}

// ---------------- head ----------------
__global__ __launch_bounds__(256) void k_head(
    const float* __restrict__ x,
    const float* __restrict__ Wh1, const float* __restrict__ bh1,
    const float* __restrict__ Wh2, const float* __restrict__ bh2,
    float* __restrict__ out)
{
    __shared__ float w1[320], b1[10], w2[100], b2[10];
    int tid = threadIdx.x;
    for (int i = tid; i < 320; i += 256) w1[i] = Wh1[i];
    for (int i = tid; i < 100; i += 256) w2[i] = Wh2[i];
    if (tid < 10) { b1[tid] = bh1[tid]; b2[tid] = bh2[tid]; }
    __syncthreads();
    int v = blockIdx.x * 256 + tid;
    if (v >= NN) return;
    float z[32];
    #pragma unroll
    for (int j = 0; j < 16; j++) {
        z[j]      = g_gout[v * 16 + j];
        z[16 + j] = x[v * 16 + j];
    }
    float t[10];
    #pragma unroll
    for (int j = 0; j < 10; j++) {
        float a = b1[j];
        #pragma unroll
        for (int i = 0; i < 32; i++) a = fmaf(z[i], w1[i * 10 + j], a);
        t[j] = fmaxf(a, 0.f);
    }
    #pragma unroll
    for (int j = 0; j < 10; j++) {
        float a = b2[j];
        #pragma unroll
        for (int k = 0; k < 10; k++) a = fmaf(t[k], w2[k * 10 + j], a);
        out[v * 10 + j] = a;
    }
}

// ---------------- driver ----------------
extern "C" void kernel_launch(void* const* d_in, const int* in_sizes, int n_in,
                              void* d_out, int out_size) {
    const float* x     = (const float*)d_in[0];
    const int*   ei    = (const int*)  d_in[1];
    const float* ea    = (const float*)d_in[2];
    const float* We0   = (const float*)d_in[3];
    const float* be0   = (const float*)d_in[4];
    const float* Wpre0 = (const float*)d_in[5];
    const float* bpre0 = (const float*)d_in[6];
    const float* Wpost0= (const float*)d_in[7];
    const float* bpost0= (const float*)d_in[8];
    const float* Wlin0 = (const float*)d_in[9];
    const float* blin0 = (const float*)d_in[10];
    const float* We1   = (const float*)d_in[11];
    const float* be1   = (const float*)d_in[12];
    const float* Wpre1 = (const float*)d_in[13];
    const float* bpre1 = (const float*)d_in[14];
    const float* Wpost1= (const float*)d_in[15];
    const float* bpost1= (const float*)d_in[16];
    const float* Wlin1 = (const float*)d_in[17];
    const float* blin1 = (const float*)d_in[18];
    const float* Wg    = (const float*)d_in[19];
    const float* bg    = (const float*)d_in[20];
    const float* Wh1   = (const float*)d_in[21];
    const float* bh1   = (const float*)d_in[22];
    const float* Wh2   = (const float*)d_in[23];
    const float* bh2   = (const float*)d_in[24];
    float* out = (float*)d_out;

    const int* srcp = ei;
    const int* dstp = ei + NE;

    float *p_h1, *p_xd, *p_xs, *p_xb1;
    cudaGetSymbolAddress((void**)&p_h1,  g_h1);
    cudaGetSymbolAddress((void**)&p_xd,  g_xd);
    cudaGetSymbolAddress((void**)&p_xs,  g_xs);
    cudaGetSymbolAddress((void**)&p_xb1, g_xb1);

    // raise dynamic smem limits (idempotent; non-stream API, capture-safe)
    cudaFuncSetAttribute(k_pna0, cudaFuncAttributeMaxDynamicSharedMemorySize, P0_SMEM);
    cudaFuncSetAttribute(k_pna1, cudaFuncAttributeMaxDynamicSharedMemorySize, P1_SMEM);

    const int EB = (NE + 255) / 256;           // 6250
    const int SB = (NN + 1023) / 1024;         // 98
    const int GB = (NN + 63) / 64;             // 1563

    // CSR build
    k_zero<<<(NN + 255) / 256, 256>>>();
    k_count<<<EB, 256>>>(dstp);
    k_scan1<<<SB, 1024>>>();
    k_scan2<<<1, 128>>>(SB);
    k_scan3<<<SB, 1024>>>();
    k_scatter<<<EB, 256>>>(srcp, dstp, ea);

    // weight folding (independent of CSR)
    k_fold_edge<<<1, 64>>>(We0, be0, Wpre0, bpre0, 16, 0);
    k_fold_edge<<<1, 64>>>(We1, be1, Wpre1, bpre1, 64, 1);
    k_fold_post<<<(96 * 64 + 64 + 255) / 256, 256>>>(Wpost0, bpost0, Wlin0, blin0, 96, 0);
    k_fold_post<<<(384 * 64 + 64 + 255) / 256, 256>>>(Wpost1, bpost1, Wlin1, blin1, 384, 1);

    // PNA layer 0 (fused agg + post GEMM)
    k_xdxs0<<<(NN * 32 + 255) / 256, 256>>>(x, Wpre0);
    k_pna0<<<GB, 256, P0_SMEM>>>(x);

    // PNA layer 1
    k_gemm64<64, false><<<GB, 256>>>(p_h1, 64, Wpre1, p_xb1, p_xd, 64, NN);          // xd1
    k_gemm64<64, false><<<GB, 256>>>(p_h1, 64, Wpre1 + 64 * 64, nullptr, p_xs, 64, NN); // xs1
    k_pna1<<<(NN + 31) / 32, 256, P1_SMEM>>>();

    // GCN
    k_gcn_hn<<<(NN + 15) / 16, 256>>>(Wg);
    k_gcn_agg<<<(NN + 15) / 16, 256>>>(bg);

    // head
    k_head<<<(NN + 255) / 256, 256>>>(x, Wh1, bh1, Wh2, bh2, out);
}

// round 6
// speedup vs baseline: 1.6872x; 1.6872x over previous
#include <cuda_runtime.h>
#include <cstdint>

#define NN 100000
#define NE 1600000

// ---------------- scratch (static __device__ — allocation-free) ----------------
__device__ int    g_deg[NN];
__device__ int    g_cursor[NN];
__device__ int    g_rowptr[NN + 1];
__device__ int    g_bsum[256];
__device__ int    g_bsrc[NE];
__device__ float4 g_battr[NE];
__device__ float  g_xd[NN * 64];
__device__ float  g_xs[NN * 64];
__device__ float  g_cat0[NN * 96];      // layer0 concat input [x | s mean mx mn std]
__device__ float  g_big[NN * 384];      // layer1 concat input
__device__ float  g_h1[NN * 64];
__device__ float  g_h2[NN * 64];
__device__ float  g_hn[NN * 16];
__device__ float  g_gout[NN * 16];
// folded weights
__device__ float  g_Wc0[4 * 16],  g_xb0[16];
__device__ float  g_Wc1[4 * 64],  g_xb1[64];
__device__ float  g_Wcomb0[96 * 64],  g_bcomb0[64];
__device__ float  g_Wcomb1[384 * 64], g_bcomb1[64];

// ---------------- CSR build ----------------
__global__ void k_zero() {
    int i = blockIdx.x * blockDim.x + threadIdx.x;
    if (i < NN) { g_deg[i] = 0; g_cursor[i] = 0; }
}

__global__ void k_count(const int* __restrict__ dst) {
    int e = blockIdx.x * blockDim.x + threadIdx.x;
    if (e < NE) atomicAdd(&g_deg[dst[e]], 1);
}

__global__ void k_scan1() {
    __shared__ int s[1024];
    int i = blockIdx.x * 1024 + threadIdx.x;
    int v = (i < NN) ? g_deg[i] : 0;
    s[threadIdx.x] = v;
    __syncthreads();
    for (int off = 1; off < 1024; off <<= 1) {
        int t = (threadIdx.x >= off) ? s[threadIdx.x - off] : 0;
        __syncthreads();
        s[threadIdx.x] += t;
        __syncthreads();
    }
    if (i < NN) g_rowptr[i] = s[threadIdx.x] - v;   // exclusive within block
    if (threadIdx.x == 1023) g_bsum[blockIdx.x] = s[1023];
}

__global__ void k_scan2(int nb) {
    __shared__ int s[128];
    int t = threadIdx.x;
    int v = (t < nb) ? g_bsum[t] : 0;
    s[t] = v;
    __syncthreads();
    for (int off = 1; off < 128; off <<= 1) {
        int u = (t >= off) ? s[t - off] : 0;
        __syncthreads();
        s[t] += u;
        __syncthreads();
    }
    if (t < nb) g_bsum[t] = s[t] - v;   // exclusive block offsets
}

__global__ void k_scan3() {
    int i = blockIdx.x * 1024 + threadIdx.x;
    if (i < NN) g_rowptr[i] += g_bsum[blockIdx.x];
    if (i == 0) g_rowptr[NN] = NE;
}

__global__ void k_scatter(const int* __restrict__ src, const int* __restrict__ dst,
                          const float* __restrict__ ea) {
    int e = blockIdx.x * blockDim.x + threadIdx.x;
    if (e >= NE) return;
    int d = dst[e];
    int p = g_rowptr[d] + atomicAdd(&g_cursor[d], 1);
    g_bsrc[p]  = src[e];
    g_battr[p] = ((const float4*)ea)[e];
}

// ---------------- weight folding ----------------
__global__ void k_fold_edge(const float* __restrict__ We, const float* __restrict__ be,
                            const float* __restrict__ Wpre, const float* __restrict__ bpre,
                            int F, int layer) {
    int f = blockIdx.x * blockDim.x + threadIdx.x;
    if (f >= F) return;
    float a0 = 0, a1 = 0, a2 = 0, a3 = 0, b = bpre[f];
    for (int j = 0; j < F; j++) {
        float wv = Wpre[(2 * F + j) * F + f];
        a0 = fmaf(We[0 * F + j], wv, a0);
        a1 = fmaf(We[1 * F + j], wv, a1);
        a2 = fmaf(We[2 * F + j], wv, a2);
        a3 = fmaf(We[3 * F + j], wv, a3);
        b  = fmaf(be[j], wv, b);
    }
    float* Wc = layer ? g_Wc1 : g_Wc0;
    float* xb = layer ? g_xb1 : g_xb0;
    Wc[0 * F + f] = a0; Wc[1 * F + f] = a1; Wc[2 * F + f] = a2; Wc[3 * F + f] = a3;
    xb[f] = b;
}

__global__ void k_fold_post(const float* __restrict__ Wpost, const float* __restrict__ bpost,
                            const float* __restrict__ Wlin, const float* __restrict__ blin,
                            int Kc, int layer) {
    int idx = blockIdx.x * blockDim.x + threadIdx.x;
    int total = Kc * 64;
    float* Wcomb = layer ? g_Wcomb1 : g_Wcomb0;
    float* bcomb = layer ? g_bcomb1 : g_bcomb0;
    if (idx < total) {
        int k = idx >> 6, f = idx & 63;
        float a = 0;
        for (int j = 0; j < 64; j++) a = fmaf(Wpost[k * 64 + j], Wlin[j * 64 + f], a);
        Wcomb[idx] = a;
    } else if (idx < total + 64) {
        int f = idx - total;
        float a = blin[f];
        for (int j = 0; j < 64; j++) a = fmaf(bpost[j], Wlin[j * 64 + f], a);
        bcomb[f] = a;
    }
}

// ---------------- layer-0 precompute: xd0/xs0 + copy x into cat0 ----------------
__global__ void k_xdxs0(const float* __restrict__ x, const float* __restrict__ Wpre0) {
    int t = blockIdx.x * blockDim.x + threadIdx.x;
    if (t >= NN * 32) return;
    int v = t >> 5, l = t & 31, f = l & 15;
    int rbase = (l < 16) ? 0 : 16;
    float acc = (l < 16) ? g_xb0[f] : 0.f;
    const float* xr = x + v * 16;
    #pragma unroll
    for (int j = 0; j < 16; j++)
        acc = fmaf(xr[j], Wpre0[(rbase + j) * 16 + f], acc);
    if (l < 16) { g_xd[v * 16 + f] = acc; g_cat0[v * 96 + f] = xr[f]; }
    else        { g_xs[v * 16 + f] = acc; }
}

// ---------------- PNA aggregation layer 0 (F=16, 16 lanes/node) ----------------
__global__ __launch_bounds__(256) void k_agg0() {
    int tid = threadIdx.x;
    int v = blockIdx.x * 16 + (tid >> 4);
    int f = tid & 15;
    if (v >= NN) return;
    int rs = g_rowptr[v], re = g_rowptr[v + 1];
    float xdv = g_xd[v * 16 + f];
    float w0 = g_Wc0[f], w1 = g_Wc0[16 + f], w2 = g_Wc0[32 + f], w3 = g_Wc0[48 + f];
    float s = 0, sq = 0, mx = -3.402823e38f, mn = 3.402823e38f;
    #pragma unroll 2
    for (int e = rs; e < re; e++) {
        int sid = g_bsrc[e];
        float4 a = g_battr[e];
        float m = xdv + g_xs[sid * 16 + f];
        m = fmaf(a.x, w0, fmaf(a.y, w1, fmaf(a.z, w2, fmaf(a.w, w3, m))));
        s += m; sq = fmaf(m, m, sq); mx = fmaxf(mx, m); mn = fminf(mn, m);
    }
    int cnt = re - rs;
    float den = (float)(cnt > 0 ? cnt : 1);
    float mean = s / den, msq = sq / den;
    float sd = sqrtf(fmaxf(msq - mean * mean, 0.f) + 1e-5f);
    if (cnt == 0) { mx = 0.f; mn = 0.f; }
    float* o = g_cat0 + v * 96 + 16 + f;
    o[0] = s; o[16] = mean; o[32] = mx; o[48] = mn; o[64] = sd;
}

// ---------------- PNA aggregation layer 1 (F=64, 64 lanes/node) ----------------
__global__ __launch_bounds__(256) void k_agg1() {
    int tid = threadIdx.x;
    int v = blockIdx.x * 4 + (tid >> 6);
    int f = tid & 63;
    if (v >= NN) return;
    int rs = g_rowptr[v], re = g_rowptr[v + 1];
    float xdv = g_xd[v * 64 + f];
    float w0 = g_Wc1[f], w1 = g_Wc1[64 + f], w2 = g_Wc1[128 + f], w3 = g_Wc1[192 + f];
    float s = 0, sq = 0, mx = -3.402823e38f, mn = 3.402823e38f;
    #pragma unroll 2
    for (int e = rs; e < re; e++) {
        int sid = g_bsrc[e];
        float4 a = g_battr[e];
        float m = xdv + g_xs[sid * 64 + f];
        m = fmaf(a.x, w0, fmaf(a.y, w1, fmaf(a.z, w2, fmaf(a.w, w3, m))));
        s += m; sq = fmaf(m, m, sq); mx = fmaxf(mx, m); mn = fminf(mn, m);
    }
    int cnt = re - rs;
    float den = (float)(cnt > 0 ? cnt : 1);
    float mean = s / den, msq = sq / den;
    float sd = sqrtf(fmaxf(msq - mean * mean, 0.f) + 1e-5f);
    if (cnt == 0) { mx = 0.f; mn = 0.f; }
    float* o = g_big + v * 384 + 64 + f;
    o[0] = s; o[64] = mean; o[128] = mx; o[192] = mn; o[256] = sd;
}

// ---------------- tiled fp32 GEMM: C[M,64] = A[M,K] @ W[K,64] (+bias)(+relu) ----------------
template<int K, bool RELU>
__global__ __launch_bounds__(256) void k_gemm64(
    const float* __restrict__ A, int lda,
    const float* __restrict__ W,
    const float* __restrict__ bias,
    float* __restrict__ C, int ldc,
    float* __restrict__ C2, int ldc2,
    int M)
{
    __shared__ float As[16][68];
    __shared__ float Bs[16][64];
    int tid = threadIdx.x;
    int tx = tid & 15, ty = tid >> 4;
    int rowBase = blockIdx.x * 64;
    float acc[4][4];
    #pragma unroll
    for (int i = 0; i < 4; i++)
        #pragma unroll
        for (int j = 0; j < 4; j++) acc[i][j] = 0.f;

    int ka = tid & 15, ra = tid >> 4;
    int cb = tid & 63, kb = tid >> 6;

    for (int kc = 0; kc < K; kc += 16) {
        #pragma unroll
        for (int i = 0; i < 4; i++) {
            int r = ra + i * 16;
            int gr = rowBase + r;
            As[ka][r] = (gr < M) ? A[gr * lda + kc + ka] : 0.f;
        }
        #pragma unroll
        for (int i = 0; i < 4; i++)
            Bs[kb + i * 4][cb] = W[(kc + kb + i * 4) * 64 + cb];
        __syncthreads();
        #pragma unroll
        for (int k = 0; k < 16; k++) {
            float4 b4 = *(const float4*)&Bs[k][tx * 4];
            float4 a4 = *(const float4*)&As[k][ty * 4];
            float av[4] = {a4.x, a4.y, a4.z, a4.w};
            float bv[4] = {b4.x, b4.y, b4.z, b4.w};
            #pragma unroll
            for (int i = 0; i < 4; i++)
                #pragma unroll
                for (int j = 0; j < 4; j++)
                    acc[i][j] = fmaf(av[i], bv[j], acc[i][j]);
        }
        __syncthreads();
    }

    int c0 = tx * 4;
    float bv[4];
    #pragma unroll
    for (int j = 0; j < 4; j++) bv[j] = bias ? bias[c0 + j] : 0.f;
    #pragma unroll
    for (int i = 0; i < 4; i++) {
        int gr = rowBase + ty * 4 + i;
        if (gr < M) {
            float4 o;
            float* po = (float*)&o;
            #pragma unroll
            for (int j = 0; j < 4; j++) {
                float v = acc[i][j] + bv[j];
                if (RELU) v = fmaxf(v, 0.f);
                po[j] = v;
            }
            *(float4*)&C[gr * ldc + c0] = o;
            if (C2) *(float4*)&C2[gr * ldc2 + c0] = o;
        }
    }
}

// ================ tf32 tensor-core GEMM: h2 = relu(big[M,384] @ Wcomb1 + bcomb1) ================
// 128 threads (4 warps), 128 rows/block, N=64, K chunks of 32.
// SMEM strides chosen for conflict-free mma fragment loads:
//   A stride 36 (36 % 32 == 4): bank = 4*(lane>>2) + (lane&3) — all 32 distinct
//   B stride 72 (72 % 32 == 8): bank = 8*(lane&3) + (lane>>2) — all 32 distinct
#define TA 36
#define TB 72

__device__ __forceinline__ uint32_t f2tf32(float v) {
    uint32_t t;
    asm("cvt.rna.tf32.f32 %0, %1;" : "=r"(t) : "f"(v));
    return t;
}

__global__ __launch_bounds__(128) void k_gemm_tf32(const float* __restrict__ A,
                                                   float* __restrict__ C) {
    __shared__ float sA[128 * TA];
    __shared__ float sB[32 * TB];
    int tid = threadIdx.x;
    int lane = tid & 31, w = tid >> 5;
    int rowBase = blockIdx.x * 128;

    float acc[2][8][4];
    #pragma unroll
    for (int mf = 0; mf < 2; mf++)
        #pragma unroll
        for (int j = 0; j < 8; j++)
            #pragma unroll
            for (int q = 0; q < 4; q++) acc[mf][j][q] = 0.f;

    for (int kc = 0; kc < 12; kc++) {
        // load A chunk: 128 rows x 32 k (coalesced: 32 consecutive k per row)
        #pragma unroll
        for (int i = 0; i < 32; i++) {
            int idx = tid + i * 128;
            int r = idx >> 5, k = idx & 31;
            int v = rowBase + r;
            float val = (v < NN) ? A[v * 384 + kc * 32 + k] : 0.f;
            sA[r * TA + k] = __uint_as_float(f2tf32(val));
        }
        // load B chunk: 32 k x 64 n
        #pragma unroll
        for (int i = 0; i < 16; i++) {
            int idx = tid + i * 128;
            int k = idx >> 6, n = idx & 63;
            sB[k * TB + n] = __uint_as_float(f2tf32(g_Wcomb1[(kc * 32 + k) * 64 + n]));
        }
        __syncthreads();
        #pragma unroll
        for (int ks = 0; ks < 4; ks++) {
            int kk = ks * 8;
            uint32_t a[2][4];
            #pragma unroll
            for (int mf = 0; mf < 2; mf++) {
                int r = w * 32 + mf * 16 + (lane >> 2);
                a[mf][0] = __float_as_uint(sA[r * TA + kk + (lane & 3)]);
                a[mf][1] = __float_as_uint(sA[(r + 8) * TA + kk + (lane & 3)]);
                a[mf][2] = __float_as_uint(sA[r * TA + kk + (lane & 3) + 4]);
                a[mf][3] = __float_as_uint(sA[(r + 8) * TA + kk + (lane & 3) + 4]);
            }
            #pragma unroll
            for (int j = 0; j < 8; j++) {
                uint32_t b0 = __float_as_uint(sB[(kk + (lane & 3)) * TB + j * 8 + (lane >> 2)]);
                uint32_t b1 = __float_as_uint(sB[(kk + (lane & 3) + 4) * TB + j * 8 + (lane >> 2)]);
                #pragma unroll
                for (int mf = 0; mf < 2; mf++) {
                    asm volatile(
                        "mma.sync.aligned.m16n8k8.row.col.f32.tf32.tf32.f32 "
                        "{%0,%1,%2,%3}, {%4,%5,%6,%7}, {%8,%9}, {%0,%1,%2,%3};"
                        : "+f"(acc[mf][j][0]), "+f"(acc[mf][j][1]),
                          "+f"(acc[mf][j][2]), "+f"(acc[mf][j][3])
                        : "r"(a[mf][0]), "r"(a[mf][1]), "r"(a[mf][2]), "r"(a[mf][3]),
                          "r"(b0), "r"(b1));
                }
            }
        }
        __syncthreads();
    }

    // epilogue: bias + relu
    #pragma unroll
    for (int mf = 0; mf < 2; mf++) {
        int r0 = w * 32 + mf * 16 + (lane >> 2);
        #pragma unroll
        for (int j = 0; j < 8; j++) {
            int col = j * 8 + (lane & 3) * 2;
            float b0 = g_bcomb1[col], b1 = g_bcomb1[col + 1];
            int v0 = rowBase + r0;
            if (v0 < NN) {
                float2 o = { fmaxf(acc[mf][j][0] + b0, 0.f),
                             fmaxf(acc[mf][j][1] + b1, 0.f) };
                *(float2*)&C[v0 * 64 + col] = o;
            }
            int v1 = rowBase + r0 + 8;
            if (v1 < NN) {
                float2 o = { fmaxf(acc[mf][j][2] + b0, 0.f),
                             fmaxf(acc[mf][j][3] + b1, 0.f) };
                *(float2*)&C[v1 * 64 + col] = o;
            }
        }
    }
}

// ---------------- GCN ----------------
__global__ __launch_bounds__(256) void k_gcn_hn(const float* __restrict__ Wg) {
    __shared__ float w[64 * 16];
    int tid = threadIdx.x;
    for (int i = tid; i < 1024; i += 256) w[i] = Wg[i];
    __syncthreads();
    int v = blockIdx.x * 16 + (tid >> 4);
    int f = tid & 15;
    if (v >= NN) return;
    const float* h = g_h2 + v * 64;
    float acc = 0;
    #pragma unroll 8
    for (int j = 0; j < 64; j++) acc = fmaf(h[j], w[j * 16 + f], acc);
    float dinv = rsqrtf((float)(g_deg[v] + 1));
    g_hn[v * 16 + f] = acc * dinv;
}

__global__ __launch_bounds__(256) void k_gcn_agg(const float* __restrict__ bg) {
    int tid = threadIdx.x;
    int v = blockIdx.x * 16 + (tid >> 4);
    int f = tid & 15;
    if (v >= NN) return;
    int rs = g_rowptr[v], re = g_rowptr[v + 1];
    float s = g_hn[v * 16 + f];                 // self loop
    #pragma unroll 2
    for (int e = rs; e < re; e++)
        s += g_hn[g_bsrc[e] * 16 + f];
    float dinv = rsqrtf((float)(g_deg[v] + 1));
    g_gout[v * 16 + f] = s * dinv + bg[f];
}

// ---------------- head ----------------
__global__ __launch_bounds__(256) void k_head(
    const float* __restrict__ x,
    const float* __restrict__ Wh1, const float* __restrict__ bh1,
    const float* __restrict__ Wh2, const float* __restrict__ bh2,
    float* __restrict__ out)
{
    __shared__ float w1[320], b1[10], w2[100], b2[10];
    int tid = threadIdx.x;
    for (int i = tid; i < 320; i += 256) w1[i] = Wh1[i];
    for (int i = tid; i < 100; i += 256) w2[i] = Wh2[i];
    if (tid < 10) { b1[tid] = bh1[tid]; b2[tid] = bh2[tid]; }
    __syncthreads();
    int v = blockIdx.x * 256 + tid;
    if (v >= NN) return;
    float z[32];
    #pragma unroll
    for (int j = 0; j < 16; j++) {
        z[j]      = g_gout[v * 16 + j];
        z[16 + j] = x[v * 16 + j];
    }
    float t[10];
    #pragma unroll
    for (int j = 0; j < 10; j++) {
        float a = b1[j];
        #pragma unroll
        for (int i = 0; i < 32; i++) a = fmaf(z[i], w1[i * 10 + j], a);
        t[j] = fmaxf(a, 0.f);
    }
    #pragma unroll
    for (int j = 0; j < 10; j++) {
        float a = b2[j];
        #pragma unroll
        for (int k = 0; k < 10; k++) a = fmaf(t[k], w2[k * 10 + j], a);
        out[v * 10 + j] = a;
    }
}

// ---------------- driver ----------------
extern "C" void kernel_launch(void* const* d_in, const int* in_sizes, int n_in,
                              void* d_out, int out_size) {
    const float* x     = (const float*)d_in[0];
    const int*   ei    = (const int*)  d_in[1];
    const float* ea    = (const float*)d_in[2];
    const float* We0   = (const float*)d_in[3];
    const float* be0   = (const float*)d_in[4];
    const float* Wpre0 = (const float*)d_in[5];
    const float* bpre0 = (const float*)d_in[6];
    const float* Wpost0= (const float*)d_in[7];
    const float* bpost0= (const float*)d_in[8];
    const float* Wlin0 = (const float*)d_in[9];
    const float* blin0 = (const float*)d_in[10];
    const float* We1   = (const float*)d_in[11];
    const float* be1   = (const float*)d_in[12];
    const float* Wpre1 = (const float*)d_in[13];
    const float* bpre1 = (const float*)d_in[14];
    const float* Wpost1= (const float*)d_in[15];
    const float* bpost1= (const float*)d_in[16];
    const float* Wlin1 = (const float*)d_in[17];
    const float* blin1 = (const float*)d_in[18];
    const float* Wg    = (const float*)d_in[19];
    const float* bg    = (const float*)d_in[20];
    const float* Wh1   = (const float*)d_in[21];
    const float* bh1   = (const float*)d_in[22];
    const float* Wh2   = (const float*)d_in[23];
    const float* bh2   = (const float*)d_in[24];
    float* out = (float*)d_out;

    const int* srcp = ei;
    const int* dstp = ei + NE;

    float *p_cat0, *p_big, *p_h1, *p_h2, *p_xd, *p_xs;
    float *p_Wcomb0, *p_bcomb0, *p_xb1;
    cudaGetSymbolAddress((void**)&p_cat0,  g_cat0);
    cudaGetSymbolAddress((void**)&p_big,   g_big);
    cudaGetSymbolAddress((void**)&p_h1,    g_h1);
    cudaGetSymbolAddress((void**)&p_h2,    g_h2);
    cudaGetSymbolAddress((void**)&p_xd,    g_xd);
    cudaGetSymbolAddress((void**)&p_xs,    g_xs);
    cudaGetSymbolAddress((void**)&p_Wcomb0,g_Wcomb0);
    cudaGetSymbolAddress((void**)&p_bcomb0,g_bcomb0);
    cudaGetSymbolAddress((void**)&p_xb1,   g_xb1);

    const int EB = (NE + 255) / 256;           // 6250
    const int SB = (NN + 1023) / 1024;         // 98
    const int GB = (NN + 63) / 64;             // 1563

    // CSR build
    k_zero<<<(NN + 255) / 256, 256>>>();
    k_count<<<EB, 256>>>(dstp);
    k_scan1<<<SB, 1024>>>();
    k_scan2<<<1, 128>>>(SB);
    k_scan3<<<SB, 1024>>>();
    k_scatter<<<EB, 256>>>(srcp, dstp, ea);

    // weight folding (independent of CSR)
    k_fold_edge<<<1, 64>>>(We0, be0, Wpre0, bpre0, 16, 0);
    k_fold_edge<<<1, 64>>>(We1, be1, Wpre1, bpre1, 64, 1);
    k_fold_post<<<(96 * 64 + 64 + 255) / 256, 256>>>(Wpost0, bpost0, Wlin0, blin0, 96, 0);
    k_fold_post<<<(384 * 64 + 64 + 255) / 256, 256>>>(Wpost1, bpost1, Wlin1, blin1, 384, 1);

    // PNA layer 0
    k_xdxs0<<<(NN * 32 + 255) / 256, 256>>>(x, Wpre0);
    k_agg0<<<(NN + 15) / 16, 256>>>();
    // h1 = relu(cat0 @ Wcomb0 + bcomb0); also write h1 into big[:, 0:64]
    k_gemm64<96, true><<<GB, 256>>>(p_cat0, 96, p_Wcomb0, p_bcomb0,
                                    p_h1, 64, p_big, 384, NN);

    // PNA layer 1
    k_gemm64<64, false><<<GB, 256>>>(p_h1, 64, Wpre1, p_xb1,
                                     p_xd, 64, (float*)nullptr, 0, NN);           // xd1
    k_gemm64<64, false><<<GB, 256>>>(p_h1, 64, Wpre1 + 64 * 64, (float*)nullptr,
                                     p_xs, 64, (float*)nullptr, 0, NN);           // xs1
    k_agg1<<<(NN + 3) / 4, 256>>>();
    // h2 = relu(big @ Wcomb1 + bcomb1)  — tf32 tensor cores
    k_gemm_tf32<<<(NN + 127) / 128, 128>>>(p_big, p_h2);

    // GCN
    k_gcn_hn<<<(NN + 15) / 16, 256>>>(Wg);
    k_gcn_agg<<<(NN + 15) / 16, 256>>>(bg);

    // head
    k_head<<<(NN + 255) / 256, 256>>>(x, Wh1, bh1, Wh2, bh2, out);
}

// round 7
// speedup vs baseline: 1.7123x; 1.0149x over previous
#include <cuda_runtime.h>
#include <cstdint>

#define NN 100000
#define NE 1600000

// ---------------- scratch (static __device__ — allocation-free) ----------------
__device__ int    g_deg[NN];
__device__ int    g_cursor[NN];
__device__ int    g_rowptr[NN + 1];
__device__ int    g_bsum[256];
__device__ int    g_bsrc[NE];
__device__ float4 g_battr[NE];
__device__ float  g_xd[NN * 64];
__device__ float  g_xs[NN * 64];
__device__ float  g_cat0[NN * 96];      // layer0 concat input [x | s mean mx mn std]
__device__ float  g_big[NN * 384];      // layer1 concat input
__device__ float  g_h1[NN * 64];
__device__ float  g_h2[NN * 64];
__device__ float  g_hn[NN * 16];
__device__ float  g_gout[NN * 16];
// folded weights
__device__ float  g_Wc0[4 * 16],  g_xb0[16];
__device__ float  g_Wc1[4 * 64],  g_xb1[64];
__device__ float  g_Wcomb0[96 * 64],  g_bcomb0[64];
__device__ float  g_Wcomb1[384 * 64], g_bcomb1[64];

// ---------------- CSR build ----------------
__global__ void k_count(const int* __restrict__ dst) {
    int e = blockIdx.x * blockDim.x + threadIdx.x;
    if (e < NE) atomicAdd(&g_deg[dst[e]], 1);
}

__global__ void k_scan1() {
    __shared__ int s[1024];
    int i = blockIdx.x * 1024 + threadIdx.x;
    int v = (i < NN) ? g_deg[i] : 0;
    s[threadIdx.x] = v;
    __syncthreads();
    for (int off = 1; off < 1024; off <<= 1) {
        int t = (threadIdx.x >= off) ? s[threadIdx.x - off] : 0;
        __syncthreads();
        s[threadIdx.x] += t;
        __syncthreads();
    }
    if (i < NN) g_rowptr[i] = s[threadIdx.x] - v;   // exclusive within block
    if (threadIdx.x == 1023) g_bsum[blockIdx.x] = s[1023];
}

__global__ void k_scan2(int nb) {
    __shared__ int s[128];
    int t = threadIdx.x;
    int v = (t < nb) ? g_bsum[t] : 0;
    s[t] = v;
    __syncthreads();
    for (int off = 1; off < 128; off <<= 1) {
        int u = (t >= off) ? s[t - off] : 0;
        __syncthreads();
        s[t] += u;
        __syncthreads();
    }
    if (t < nb) g_bsum[t] = s[t] - v;   // exclusive block offsets
}

__global__ void k_scan3() {
    int i = blockIdx.x * 1024 + threadIdx.x;
    if (i < NN) {
        g_rowptr[i] += g_bsum[blockIdx.x];
        g_cursor[i] = 0;
    }
    if (i == 0) g_rowptr[NN] = NE;
}

__global__ void k_scatter(const int* __restrict__ src, const int* __restrict__ dst,
                          const float* __restrict__ ea) {
    int e = blockIdx.x * blockDim.x + threadIdx.x;
    if (e >= NE) return;
    int d = dst[e];
    int p = g_rowptr[d] + atomicAdd(&g_cursor[d], 1);
    g_bsrc[p]  = src[e];
    g_battr[p] = ((const float4*)ea)[e];
}

// ---------------- weight folding ----------------
__global__ void k_fold_edge(const float* __restrict__ We, const float* __restrict__ be,
                            const float* __restrict__ Wpre, const float* __restrict__ bpre,
                            int F, int layer) {
    int f = blockIdx.x * blockDim.x + threadIdx.x;
    if (f >= F) return;
    float a0 = 0, a1 = 0, a2 = 0, a3 = 0, b = bpre[f];
    for (int j = 0; j < F; j++) {
        float wv = Wpre[(2 * F + j) * F + f];
        a0 = fmaf(We[0 * F + j], wv, a0);
        a1 = fmaf(We[1 * F + j], wv, a1);
        a2 = fmaf(We[2 * F + j], wv, a2);
        a3 = fmaf(We[3 * F + j], wv, a3);
        b  = fmaf(be[j], wv, b);
    }
    float* Wc = layer ? g_Wc1 : g_Wc0;
    float* xb = layer ? g_xb1 : g_xb0;
    Wc[0 * F + f] = a0; Wc[1 * F + f] = a1; Wc[2 * F + f] = a2; Wc[3 * F + f] = a3;
    xb[f] = b;
}

__global__ void k_fold_post(const float* __restrict__ Wpost, const float* __restrict__ bpost,
                            const float* __restrict__ Wlin, const float* __restrict__ blin,
                            int Kc, int layer) {
    int idx = blockIdx.x * blockDim.x + threadIdx.x;
    int total = Kc * 64;
    float* Wcomb = layer ? g_Wcomb1 : g_Wcomb0;
    float* bcomb = layer ? g_bcomb1 : g_bcomb0;
    if (idx < total) {
        int k = idx >> 6, f = idx & 63;
        float a = 0;
        for (int j = 0; j < 64; j++) a = fmaf(Wpost[k * 64 + j], Wlin[j * 64 + f], a);
        Wcomb[idx] = a;
    } else if (idx < total + 64) {
        int f = idx - total;
        float a = blin[f];
        for (int j = 0; j < 64; j++) a = fmaf(bpost[j], Wlin[j * 64 + f], a);
        bcomb[f] = a;
    }
}

// ---------------- layer-0 precompute: xd0/xs0 + copy x into cat0 ----------------
__global__ void k_xdxs0(const float* __restrict__ x, const float* __restrict__ Wpre0) {
    int t = blockIdx.x * blockDim.x + threadIdx.x;
    if (t >= NN * 32) return;
    int v = t >> 5, l = t & 31, f = l & 15;
    int rbase = (l < 16) ? 0 : 16;
    float acc = (l < 16) ? g_xb0[f] : 0.f;
    const float* xr = x + v * 16;
    #pragma unroll
    for (int j = 0; j < 16; j++)
        acc = fmaf(xr[j], Wpre0[(rbase + j) * 16 + f], acc);
    if (l < 16) { g_xd[v * 16 + f] = acc; g_cat0[v * 96 + f] = xr[f]; }
    else        { g_xs[v * 16 + f] = acc; }
}

// ---------------- PNA aggregation layer 0 (F=16, 16 lanes/node) ----------------
__global__ __launch_bounds__(256) void k_agg0() {
    int tid = threadIdx.x;
    int v = blockIdx.x * 16 + (tid >> 4);
    int f = tid & 15;
    if (v >= NN) return;
    int rs = g_rowptr[v], re = g_rowptr[v + 1];
    float xdv = g_xd[v * 16 + f];
    float w0 = g_Wc0[f], w1 = g_Wc0[16 + f], w2 = g_Wc0[32 + f], w3 = g_Wc0[48 + f];
    float s = 0, sq = 0, mx = -3.402823e38f, mn = 3.402823e38f;
    #pragma unroll 2
    for (int e = rs; e < re; e++) {
        int sid = g_bsrc[e];
        float4 a = g_battr[e];
        float m = xdv + g_xs[sid * 16 + f];
        m = fmaf(a.x, w0, fmaf(a.y, w1, fmaf(a.z, w2, fmaf(a.w, w3, m))));
        s += m; sq = fmaf(m, m, sq); mx = fmaxf(mx, m); mn = fminf(mn, m);
    }
    int cnt = re - rs;
    float den = (float)(cnt > 0 ? cnt : 1);
    float mean = s / den, msq = sq / den;
    float sd = sqrtf(fmaxf(msq - mean * mean, 0.f) + 1e-5f);
    if (cnt == 0) { mx = 0.f; mn = 0.f; }
    float* o = g_cat0 + v * 96 + 16 + f;
    o[0] = s; o[16] = mean; o[32] = mx; o[48] = mn; o[64] = sd;
}

// ---------------- PNA aggregation layer 1 (F=64, 64 lanes/node) ----------------
__global__ __launch_bounds__(256) void k_agg1() {
    int tid = threadIdx.x;
    int v = blockIdx.x * 4 + (tid >> 6);
    int f = tid & 63;
    if (v >= NN) return;
    int rs = g_rowptr[v], re = g_rowptr[v + 1];
    float xdv = g_xd[v * 64 + f];
    float w0 = g_Wc1[f], w1 = g_Wc1[64 + f], w2 = g_Wc1[128 + f], w3 = g_Wc1[192 + f];
    float s = 0, sq = 0, mx = -3.402823e38f, mn = 3.402823e38f;
    #pragma unroll 2
    for (int e = rs; e < re; e++) {
        int sid = g_bsrc[e];
        float4 a = g_battr[e];
        float m = xdv + g_xs[sid * 64 + f];
        m = fmaf(a.x, w0, fmaf(a.y, w1, fmaf(a.z, w2, fmaf(a.w, w3, m))));
        s += m; sq = fmaf(m, m, sq); mx = fmaxf(mx, m); mn = fminf(mn, m);
    }
    int cnt = re - rs;
    float den = (float)(cnt > 0 ? cnt : 1);
    float mean = s / den, msq = sq / den;
    float sd = sqrtf(fmaxf(msq - mean * mean, 0.f) + 1e-5f);
    if (cnt == 0) { mx = 0.f; mn = 0.f; }
    float* o = g_big + v * 384 + 64 + f;
    o[0] = s; o[64] = mean; o[128] = mx; o[192] = mn; o[256] = sd;
}

// ================ tf32 tensor-core GEMM: C[M,64] = A[M,KC*32] @ W + bias ================
// 128 threads (4 warps), 128 rows/block, N=64, K chunks of 32.
// SMEM strides for conflict-free mma fragment loads:
//   A stride 36 (mod 32 == 4), B stride 72 (mod 32 == 8) — both full-warp conflict-free.
#define TA 36
#define TB 72

__device__ __forceinline__ uint32_t f2tf32(float v) {
    uint32_t t;
    asm("cvt.rna.tf32.f32 %0, %1;" : "=r"(t) : "f"(v));
    return t;
}

template<int KC, bool RELU>
__global__ __launch_bounds__(128) void k_gemm_tf32(
    const float* __restrict__ A, int lda,
    const float* __restrict__ W,       // [KC*32, 64] fp32 (global)
    const float* __restrict__ bias,    // [64] or nullptr
    float* __restrict__ C, int ldc,
    float* __restrict__ C2, int ldc2)  // optional second store (nullptr to skip)
{
    __shared__ float sA[128 * TA];
    __shared__ float sB[32 * TB];
    int tid = threadIdx.x;
    int lane = tid & 31, w = tid >> 5;
    int rowBase = blockIdx.x * 128;

    float acc[2][8][4];
    #pragma unroll
    for (int mf = 0; mf < 2; mf++)
        #pragma unroll
        for (int j = 0; j < 8; j++)
            #pragma unroll
            for (int q = 0; q < 4; q++) acc[mf][j][q] = 0.f;

    for (int kc = 0; kc < KC; kc++) {
        // load A chunk: 128 rows x 32 k
        #pragma unroll
        for (int i = 0; i < 32; i++) {
            int idx = tid + i * 128;
            int r = idx >> 5, k = idx & 31;
            int v = rowBase + r;
            float val = (v < NN) ? A[v * lda + kc * 32 + k] : 0.f;
            sA[r * TA + k] = __uint_as_float(f2tf32(val));
        }
        // load B chunk: 32 k x 64 n
        #pragma unroll
        for (int i = 0; i < 16; i++) {
            int idx = tid + i * 128;
            int k = idx >> 6, n = idx & 63;
            sB[k * TB + n] = __uint_as_float(f2tf32(W[(kc * 32 + k) * 64 + n]));
        }
        __syncthreads();
        #pragma unroll
        for (int ks = 0; ks < 4; ks++) {
            int kk = ks * 8;
            uint32_t a[2][4];
            #pragma unroll
            for (int mf = 0; mf < 2; mf++) {
                int r = w * 32 + mf * 16 + (lane >> 2);
                a[mf][0] = __float_as_uint(sA[r * TA + kk + (lane & 3)]);
                a[mf][1] = __float_as_uint(sA[(r + 8) * TA + kk + (lane & 3)]);
                a[mf][2] = __float_as_uint(sA[r * TA + kk + (lane & 3) + 4]);
                a[mf][3] = __float_as_uint(sA[(r + 8) * TA + kk + (lane & 3) + 4]);
            }
            #pragma unroll
            for (int j = 0; j < 8; j++) {
                uint32_t b0 = __float_as_uint(sB[(kk + (lane & 3)) * TB + j * 8 + (lane >> 2)]);
                uint32_t b1 = __float_as_uint(sB[(kk + (lane & 3) + 4) * TB + j * 8 + (lane >> 2)]);
                #pragma unroll
                for (int mf = 0; mf < 2; mf++) {
                    asm volatile(
                        "mma.sync.aligned.m16n8k8.row.col.f32.tf32.tf32.f32 "
                        "{%0,%1,%2,%3}, {%4,%5,%6,%7}, {%8,%9}, {%0,%1,%2,%3};"
                        : "+f"(acc[mf][j][0]), "+f"(acc[mf][j][1]),
                          "+f"(acc[mf][j][2]), "+f"(acc[mf][j][3])
                        : "r"(a[mf][0]), "r"(a[mf][1]), "r"(a[mf][2]), "r"(a[mf][3]),
                          "r"(b0), "r"(b1));
                }
            }
        }
        __syncthreads();
    }

    // epilogue: bias + (relu) + store (optionally twice)
    #pragma unroll
    for (int mf = 0; mf < 2; mf++) {
        int r0 = w * 32 + mf * 16 + (lane >> 2);
        #pragma unroll
        for (int j = 0; j < 8; j++) {
            int col = j * 8 + (lane & 3) * 2;
            float b0 = bias ? bias[col] : 0.f;
            float b1 = bias ? bias[col + 1] : 0.f;
            int v0 = rowBase + r0;
            if (v0 < NN) {
                float c0 = acc[mf][j][0] + b0, c1 = acc[mf][j][1] + b1;
                if (RELU) { c0 = fmaxf(c0, 0.f); c1 = fmaxf(c1, 0.f); }
                float2 o = {c0, c1};
                *(float2*)&C[v0 * ldc + col] = o;
                if (C2) *(float2*)&C2[v0 * ldc2 + col] = o;
            }
            int v1 = rowBase + r0 + 8;
            if (v1 < NN) {
                float c0 = acc[mf][j][2] + b0, c1 = acc[mf][j][3] + b1;
                if (RELU) { c0 = fmaxf(c0, 0.f); c1 = fmaxf(c1, 0.f); }
                float2 o = {c0, c1};
                *(float2*)&C[v1 * ldc + col] = o;
                if (C2) *(float2*)&C2[v1 * ldc2 + col] = o;
            }
        }
    }
}

// ---------------- GCN ----------------
__global__ __launch_bounds__(256) void k_gcn_hn(const float* __restrict__ Wg) {
    __shared__ float w[64 * 16];
    int tid = threadIdx.x;
    for (int i = tid; i < 1024; i += 256) w[i] = Wg[i];
    __syncthreads();
    int v = blockIdx.x * 16 + (tid >> 4);
    int f = tid & 15;
    if (v >= NN) return;
    const float* h = g_h2 + v * 64;
    float acc = 0;
    #pragma unroll 8
    for (int j = 0; j < 64; j++) acc = fmaf(h[j], w[j * 16 + f], acc);
    float dinv = rsqrtf((float)(g_deg[v] + 1));
    g_hn[v * 16 + f] = acc * dinv;
}

__global__ __launch_bounds__(256) void k_gcn_agg(const float* __restrict__ bg) {
    int tid = threadIdx.x;
    int v = blockIdx.x * 16 + (tid >> 4);
    int f = tid & 15;
    if (v >= NN) return;
    int rs = g_rowptr[v], re = g_rowptr[v + 1];
    float s = g_hn[v * 16 + f];                 // self loop
    #pragma unroll 2
    for (int e = rs; e < re; e++)
        s += g_hn[g_bsrc[e] * 16 + f];
    float dinv = rsqrtf((float)(g_deg[v] + 1));
    g_gout[v * 16 + f] = s * dinv + bg[f];
}

// ---------------- head ----------------
__global__ __launch_bounds__(256) void k_head(
    const float* __restrict__ x,
    const float* __restrict__ Wh1, const float* __restrict__ bh1,
    const float* __restrict__ Wh2, const float* __restrict__ bh2,
    float* __restrict__ out)
{
    __shared__ float w1[320], b1[10], w2[100], b2[10];
    int tid = threadIdx.x;
    for (int i = tid; i < 320; i += 256) w1[i] = Wh1[i];
    for (int i = tid; i < 100; i += 256) w2[i] = Wh2[i];
    if (tid < 10) { b1[tid] = bh1[tid]; b2[tid] = bh2[tid]; }
    __syncthreads();
    int v = blockIdx.x * 256 + tid;
    if (v >= NN) return;
    float z[32];
    #pragma unroll
    for (int j = 0; j < 16; j++) {
        z[j]      = g_gout[v * 16 + j];
        z[16 + j] = x[v * 16 + j];
    }
    float t[10];
    #pragma unroll
    for (int j = 0; j < 10; j++) {
        float a = b1[j];
        #pragma unroll
        for (int i = 0; i < 32; i++) a = fmaf(z[i], w1[i * 10 + j], a);
        t[j] = fmaxf(a, 0.f);
    }
    #pragma unroll
    for (int j = 0; j < 10; j++) {
        float a = b2[j];
        #pragma unroll
        for (int k = 0; k < 10; k++) a = fmaf(t[k], w2[k * 10 + j], a);
        out[v * 10 + j] = a;
    }
}

// ---------------- driver ----------------
extern "C" void kernel_launch(void* const* d_in, const int* in_sizes, int n_in,
                              void* d_out, int out_size) {
    const float* x     = (const float*)d_in[0];
    const int*   ei    = (const int*)  d_in[1];
    const float* ea    = (const float*)d_in[2];
    const float* We0   = (const float*)d_in[3];
    const float* be0   = (const float*)d_in[4];
    const float* Wpre0 = (const float*)d_in[5];
    const float* bpre0 = (const float*)d_in[6];
    const float* Wpost0= (const float*)d_in[7];
    const float* bpost0= (const float*)d_in[8];
    const float* Wlin0 = (const float*)d_in[9];
    const float* blin0 = (const float*)d_in[10];
    const float* We1   = (const float*)d_in[11];
    const float* be1   = (const float*)d_in[12];
    const float* Wpre1 = (const float*)d_in[13];
    const float* bpre1 = (const float*)d_in[14];
    const float* Wpost1= (const float*)d_in[15];
    const float* bpost1= (const float*)d_in[16];
    const float* Wlin1 = (const float*)d_in[17];
    const float* blin1 = (const float*)d_in[18];
    const float* Wg    = (const float*)d_in[19];
    const float* bg    = (const float*)d_in[20];
    const float* Wh1   = (const float*)d_in[21];
    const float* bh1   = (const float*)d_in[22];
    const float* Wh2   = (const float*)d_in[23];
    const float* bh2   = (const float*)d_in[24];
    float* out = (float*)d_out;

    const int* srcp = ei;
    const int* dstp = ei + NE;

    float *p_cat0, *p_big, *p_h1, *p_h2, *p_xd, *p_xs;
    float *p_Wcomb0, *p_bcomb0, *p_Wcomb1, *p_bcomb1, *p_xb1;
    int   *p_deg;
    cudaGetSymbolAddress((void**)&p_cat0,  g_cat0);
    cudaGetSymbolAddress((void**)&p_big,   g_big);
    cudaGetSymbolAddress((void**)&p_h1,    g_h1);
    cudaGetSymbolAddress((void**)&p_h2,    g_h2);
    cudaGetSymbolAddress((void**)&p_xd,    g_xd);
    cudaGetSymbolAddress((void**)&p_xs,    g_xs);
    cudaGetSymbolAddress((void**)&p_Wcomb0,g_Wcomb0);
    cudaGetSymbolAddress((void**)&p_bcomb0,g_bcomb0);
    cudaGetSymbolAddress((void**)&p_Wcomb1,g_Wcomb1);
    cudaGetSymbolAddress((void**)&p_bcomb1,g_bcomb1);
    cudaGetSymbolAddress((void**)&p_xb1,   g_xb1);
    cudaGetSymbolAddress((void**)&p_deg,   g_deg);

    const int EB = (NE + 255) / 256;           // 6250
    const int SB = (NN + 1023) / 1024;         // 98
    const int TG = (NN + 127) / 128;           // 782 (tf32 gemm grid)

    // CSR build
    cudaMemsetAsync(p_deg, 0, NN * sizeof(int));
    k_count<<<EB, 256>>>(dstp);
    k_scan1<<<SB, 1024>>>();
    k_scan2<<<1, 128>>>(SB);
    k_scan3<<<SB, 1024>>>();
    k_scatter<<<EB, 256>>>(srcp, dstp, ea);

    // weight folding (independent of CSR)
    k_fold_edge<<<1, 64>>>(We0, be0, Wpre0, bpre0, 16, 0);
    k_fold_edge<<<1, 64>>>(We1, be1, Wpre1, bpre1, 64, 1);
    k_fold_post<<<(96 * 64 + 64 + 255) / 256, 256>>>(Wpost0, bpost0, Wlin0, blin0, 96, 0);
    k_fold_post<<<(384 * 64 + 64 + 255) / 256, 256>>>(Wpost1, bpost1, Wlin1, blin1, 384, 1);

    // PNA layer 0
    k_xdxs0<<<(NN * 32 + 255) / 256, 256>>>(x, Wpre0);
    k_agg0<<<(NN + 15) / 16, 256>>>();
    // h1 = relu(cat0 @ Wcomb0 + bcomb0); dual-store into big[:, 0:64]
    k_gemm_tf32<3, true><<<TG, 128>>>(p_cat0, 96, p_Wcomb0, p_bcomb0,
                                      p_h1, 64, p_big, 384);

    // PNA layer 1
    k_gemm_tf32<2, false><<<TG, 128>>>(p_h1, 64, Wpre1, p_xb1,
                                       p_xd, 64, (float*)nullptr, 0);            // xd1
    k_gemm_tf32<2, false><<<TG, 128>>>(p_h1, 64, Wpre1 + 64 * 64, (float*)nullptr,
                                       p_xs, 64, (float*)nullptr, 0);            // xs1
    k_agg1<<<(NN + 3) / 4, 256>>>();
    // h2 = relu(big @ Wcomb1 + bcomb1)
    k_gemm_tf32<12, true><<<TG, 128>>>(p_big, 384, p_Wcomb1, p_bcomb1,
                                       p_h2, 64, (float*)nullptr, 0);

    // GCN
    k_gcn_hn<<<(NN + 15) / 16, 256>>>(Wg);
    k_gcn_agg<<<(NN + 15) / 16, 256>>>(bg);

    // head
    k_head<<<(NN + 255) / 256, 256>>>(x, Wh1, bh1, Wh2, bh2, out);
}